// round 3
// baseline (speedup 1.0000x reference)
#include <cuda_runtime.h>
#include <cuda_bf16.h>
#include <cstdint>

// ============================ PTX helpers (non-'a' target safe) ============================
__device__ __forceinline__ uint32_t smem_to_u32(const void* smem_ptr) {
    uint32_t addr;
    asm("{ .reg .u64 tmp; cvta.to.shared.u64 tmp, %1; cvt.u32.u64 %0, tmp; }"
        : "=r"(addr) : "l"(smem_ptr));
    return addr;
}

#define CP_ASYNC16(dst_u32, src_ptr) \
    asm volatile("cp.async.cg.shared.global [%0], [%1], 16;" \
                 :: "r"(dst_u32), "l"(src_ptr) : "memory")
#define CP_COMMIT() asm volatile("cp.async.commit_group;" ::: "memory")
#define CP_WAIT0()  asm volatile("cp.async.wait_group 0;" ::: "memory")

#define LDSM_X4(r0, r1, r2, r3, addr) \
    asm volatile("ldmatrix.sync.aligned.m8n8.x4.shared.b16 {%0,%1,%2,%3}, [%4];" \
                 : "=r"(r0), "=r"(r1), "=r"(r2), "=r"(r3) : "r"(addr))

#define MMA16816(d, a, b0, b1) \
    asm volatile("mma.sync.aligned.m16n8k16.row.col.f32.bf16.bf16.f32 " \
                 "{%0,%1,%2,%3}, {%4,%5,%6,%7}, {%8,%9}, {%0,%1,%2,%3};" \
                 : "+f"((d)[0]), "+f"((d)[1]), "+f"((d)[2]), "+f"((d)[3]) \
                 : "r"((a)[0]), "r"((a)[1]), "r"((a)[2]), "r"((a)[3]), \
                   "r"(b0), "r"(b1))

__device__ __forceinline__ uint32_t swz128(uint32_t off) {
    return off ^ ((off >> 3) & 0x70);
}
__device__ __forceinline__ uint32_t pack_bf16x2(__nv_bfloat16 a, __nv_bfloat16 b) {
    __nv_bfloat162 t = __halves2bfloat162(a, b);  // a -> low 16 bits
    return *reinterpret_cast<uint32_t*>(&t);
}
__device__ __forceinline__ uint32_t pack_f2bf(float a, float b) {
    __nv_bfloat162 t = __floats2bfloat162_rn(a, b);
    return *reinterpret_cast<uint32_t*>(&t);
}

// ============================ problem constants ============================
static constexpr int NTOK   = 8192;
static constexpr int FEAT   = 128;
static constexpr int KC     = 64;              // K per chunk (64 bf16 = 128B row)
static constexpr int NCHUNK = NTOK / KC;       // 128
static constexpr int KSPLIT = 2;
static constexpr int NC_PER = NCHUNK / KSPLIT; // 64
static constexpr int CHUNK_BYTES = FEAT * 128; // 16384

// ============================ device scratch ============================
__device__ __align__(16) unsigned char g_xwT_hi[NCHUNK * CHUNK_BYTES];
__device__ __align__(16) unsigned char g_xwT_lo[NCHUNK * CHUNK_BYTES];
__device__ __align__(16) unsigned char g_B2_hi [NCHUNK * CHUNK_BYTES];
__device__ __align__(16) unsigned char g_B2_lo [NCHUNK * CHUNK_BYTES];
__device__ __align__(16) float g_part[KSPLIT * NTOK * FEAT];
__device__ __align__(16) float g_scale[NTOK];

// ============================ kernel 1: xw = x @ W, split, chunk layout ============================
__global__ void xw_kernel(const float* __restrict__ x, const float* __restrict__ W) {
    extern __shared__ float sh[];
    float* Ws = sh;             // 128*128
    float* xs = sh + 16384;     // 16*128
    const int t = threadIdx.x;  // 0..127 (n index)
    const int rowbase = blockIdx.x * 16;

    for (int i = t; i < 16384; i += 128) Ws[i] = W[i];
    for (int i = t; i < 2048;  i += 128) xs[i] = x[(size_t)rowbase * 128 + i];
    __syncthreads();

    #pragma unroll 1
    for (int r2 = 0; r2 < 8; r2++) {
        float a0 = 0.f, a1 = 0.f;
        const float* x0 = xs + (2 * r2) * 128;
        const float* x1 = x0 + 128;
        #pragma unroll 8
        for (int k = 0; k < 128; k++) {
            float w = Ws[k * 128 + t];
            a0 = fmaf(x0[k], w, a0);
            a1 = fmaf(x1[k], w, a1);
        }
        int kg = rowbase + 2 * r2;
        int chunk = kg >> 6;
        int c = kg & 63;
        uint32_t off = swz128((uint32_t)t * 128u + (uint32_t)c * 2u);
        __nv_bfloat16 h0 = __float2bfloat16_rn(a0);
        __nv_bfloat16 h1 = __float2bfloat16_rn(a1);
        float l0 = a0 - __bfloat162float(h0);
        float l1 = a1 - __bfloat162float(h1);
        *(uint32_t*)(g_xwT_hi + (size_t)chunk * CHUNK_BYTES + off) = pack_bf16x2(h0, h1);
        *(uint32_t*)(g_xwT_lo + (size_t)chunk * CHUNK_BYTES + off) = pack_f2bf(l0, l1);
    }
}

// ============================ kernel 2: scale = sum_j d^2 * f ============================
__global__ void scale_kernel(const float* __restrict__ d_list, const float* __restrict__ filt) {
    int n = blockIdx.x * 256 + threadIdx.x;
    float s = 0.f;
    #pragma unroll
    for (int j = 0; j < 3; j++) {
        float d = d_list[j * NTOK + n];
        float f = filt[j * NTOK + n];
        s = fmaf(d * d, f, s);
    }
    g_scale[n] = s;
}

// ============================ big GEMM via mma.sync (bf16 hi/lo split) ============================
// grid (64 Mtiles, 2 ksplits), block 256 (8 warps), dynamic smem 2 x 64KB (+align)
// Stage layout: [0,16K) A_hi  [16K,32K) A_lo  [32K,48K) B_hi  [48K,64K) B_lo
__global__ __launch_bounds__(256, 1)
void gemm_split_kernel(const float* __restrict__ A, int bsel) {
    extern __shared__ unsigned char dynsmem[];

    const unsigned char* Bhi = bsel ? g_B2_hi : g_xwT_hi;
    const unsigned char* Blo = bsel ? g_B2_lo : g_xwT_lo;

    const int tid = threadIdx.x;
    const int wid = tid >> 5;
    const int lid = tid & 31;
    const int mbase = blockIdx.x * 128;
    const int ks = blockIdx.y;
    const int kbase = ks * (NTOK / KSPLIT);
    const int chunk0 = ks * NC_PER;

    const int wm = (wid >> 2) * 64;   // warp M offset (0 or 64)
    const int wn = (wid & 3) * 32;    // warp N offset (0,32,64,96)

    uint32_t smem_u = smem_to_u32(dynsmem);
    uint32_t base = (smem_u + 1023u) & ~1023u;
    unsigned char* sb = dynsmem + (base - smem_u);

    // accumulators: 4 m16-tiles x 4 n8-tiles x 4 floats
    float acc[4][4][4];
    #pragma unroll
    for (int i = 0; i < 4; i++)
        #pragma unroll
        for (int j = 0; j < 4; j++)
            #pragma unroll
            for (int q = 0; q < 4; q++) acc[i][j][q] = 0.f;

    float4 aReg[8];

    auto ldg_chunk = [&](int chunk) {
        #pragma unroll
        for (int i = 0; i < 8; i++) {
            int idx = tid + i * 256;
            int row = idx >> 4;
            int c4 = idx & 15;
            const float* src = A + (size_t)(mbase + row) * NTOK + kbase + chunk * KC + c4 * 4;
            aReg[i] = *reinterpret_cast<const float4*>(src);
        }
    };
    auto cpasync_b = [&](int chunk, int s) {
        unsigned char* st = sb + s * 65536;
        const unsigned char* bh = Bhi + (size_t)(chunk0 + chunk) * CHUNK_BYTES;
        const unsigned char* bl = Blo + (size_t)(chunk0 + chunk) * CHUNK_BYTES;
        uint32_t dsth = base + s * 65536 + 32768;
        uint32_t dstl = dsth + 16384;
        (void)st;
        #pragma unroll
        for (int i = 0; i < 4; i++) {
            int off = (tid + i * 256) * 16;
            CP_ASYNC16(dsth + off, bh + off);
            CP_ASYNC16(dstl + off, bl + off);
        }
        CP_COMMIT();
    };
    auto sts_a = [&](int s) {
        unsigned char* st = sb + s * 65536;
        #pragma unroll
        for (int i = 0; i < 8; i++) {
            int idx = tid + i * 256;
            int row = idx >> 4;
            int c4 = idx & 15;
            uint32_t sw = swz128((uint32_t)(row * 128 + c4 * 8));
            float4 v = aReg[i];
            __nv_bfloat16 hx = __float2bfloat16_rn(v.x);
            __nv_bfloat16 hy = __float2bfloat16_rn(v.y);
            __nv_bfloat16 hz = __float2bfloat16_rn(v.z);
            __nv_bfloat16 hw = __float2bfloat16_rn(v.w);
            float rx = v.x - __bfloat162float(hx);
            float ry = v.y - __bfloat162float(hy);
            float rz = v.z - __bfloat162float(hz);
            float rw = v.w - __bfloat162float(hw);
            *(uint2*)(st + sw)         = make_uint2(pack_bf16x2(hx, hy), pack_bf16x2(hz, hw));
            *(uint2*)(st + 16384 + sw) = make_uint2(pack_f2bf(rx, ry), pack_f2bf(rz, rw));
        }
    };

    // per-lane ldmatrix address components
    const int l7  = lid & 7;
    const int mat = lid >> 3;
    // A: row = wm + i*16 + l7 + (mat&1)*8 ; kbyte = kb + (mat>>1)*16
    const int a_row_base = wm + l7 + (mat & 1) * 8;
    const int a_kb_add   = (mat >> 1) * 16;
    // B: n = wn + g*16 + l7 + (mat>>1)*8 ; kbyte = kb + (mat&1)*16
    const int b_row_base = wn + l7 + (mat >> 1) * 8;
    const int b_kb_add   = (mat & 1) * 16;

    auto compute_stage = [&](int s) {
        uint32_t sAh = base + s * 65536;
        uint32_t sAl = sAh + 16384;
        uint32_t sBh = sAh + 32768;
        uint32_t sBl = sAh + 49152;
        #pragma unroll
        for (int kk = 0; kk < 4; kk++) {
            const int kb = kk * 32;
            uint32_t ah[4][4], al[4][4], bh[4][2], bl[4][2];
            #pragma unroll
            for (int i = 0; i < 4; i++) {
                int row = a_row_base + i * 16;
                uint32_t off = (uint32_t)row * 128u + (uint32_t)((kb + a_kb_add) ^ ((row & 7) << 4));
                LDSM_X4(ah[i][0], ah[i][1], ah[i][2], ah[i][3], sAh + off);
                LDSM_X4(al[i][0], al[i][1], al[i][2], al[i][3], sAl + off);
            }
            #pragma unroll
            for (int g = 0; g < 2; g++) {
                int row = b_row_base + g * 16;
                uint32_t off = (uint32_t)row * 128u + (uint32_t)((kb + b_kb_add) ^ ((row & 7) << 4));
                uint32_t r0, r1, r2, r3;
                LDSM_X4(r0, r1, r2, r3, sBh + off);
                bh[2 * g][0] = r0; bh[2 * g][1] = r1;
                bh[2 * g + 1][0] = r2; bh[2 * g + 1][1] = r3;
                LDSM_X4(r0, r1, r2, r3, sBl + off);
                bl[2 * g][0] = r0; bl[2 * g][1] = r1;
                bl[2 * g + 1][0] = r2; bl[2 * g + 1][1] = r3;
            }
            #pragma unroll
            for (int i = 0; i < 4; i++) {
                #pragma unroll
                for (int j = 0; j < 4; j++) {
                    MMA16816(acc[i][j], ah[i], bh[j][0], bh[j][1]);
                    MMA16816(acc[i][j], ah[i], bl[j][0], bl[j][1]);
                    MMA16816(acc[i][j], al[i], bh[j][0], bh[j][1]);
                }
            }
        }
    };

    // prologue: fill stage 0
    ldg_chunk(0);
    cpasync_b(0, 0);
    sts_a(0);
    CP_WAIT0();
    __syncthreads();

    for (int i = 0; i < NC_PER; i++) {
        int b = i & 1;
        if (i + 1 < NC_PER) {
            ldg_chunk(i + 1);
            cpasync_b(i + 1, b ^ 1);
        }
        compute_stage(b);
        if (i + 1 < NC_PER) {
            sts_a(b ^ 1);
            CP_WAIT0();
        }
        __syncthreads();
    }

    // epilogue: write accumulators to g_part
    float* Pout = g_part + (size_t)ks * (NTOK * FEAT);
    const int r0 = mbase + wm + (lid >> 2);
    const int c0 = wn + (lid & 3) * 2;
    #pragma unroll
    for (int i = 0; i < 4; i++) {
        #pragma unroll
        for (int j = 0; j < 4; j++) {
            float* p = Pout + (size_t)(r0 + i * 16) * FEAT + c0 + j * 8;
            *reinterpret_cast<float2*>(p)               = make_float2(acc[i][j][0], acc[i][j][1]);
            *reinterpret_cast<float2*>(p + 8 * FEAT)    = make_float2(acc[i][j][2], acc[i][j][3]);
        }
    }
}

// ============================ reduce1: combine splits, scale, split to B2 layout ============================
__global__ void reduce1_kernel() {
    const int n = threadIdx.x;
    const int m0 = blockIdx.x * 2;
    const float s0 = g_scale[m0];
    const float s1 = g_scale[m0 + 1];
    const float* P0 = g_part;
    const float* P1 = g_part + NTOK * FEAT;
    float v0 = (P0[(size_t)m0 * FEAT + n] + P1[(size_t)m0 * FEAT + n]) * s0;
    float v1 = (P0[(size_t)(m0 + 1) * FEAT + n] + P1[(size_t)(m0 + 1) * FEAT + n]) * s1;
    __nv_bfloat16 h0 = __float2bfloat16_rn(v0);
    __nv_bfloat16 h1 = __float2bfloat16_rn(v1);
    float l0 = v0 - __bfloat162float(h0);
    float l1 = v1 - __bfloat162float(h1);
    int chunk = m0 >> 6;
    int c = m0 & 63;
    uint32_t off = swz128((uint32_t)n * 128u + (uint32_t)c * 2u);
    *(uint32_t*)(g_B2_hi + (size_t)chunk * CHUNK_BYTES + off) = pack_bf16x2(h0, h1);
    *(uint32_t*)(g_B2_lo + (size_t)chunk * CHUNK_BYTES + off) = pack_f2bf(l0, l1);
}

// ============================ reduce2: out = P0 + P1 + bias ============================
__global__ void reduce2_kernel(const float* __restrict__ bias, float* __restrict__ out) {
    int idx = blockIdx.x * 256 + threadIdx.x;
    const float4* P0 = reinterpret_cast<const float4*>(g_part);
    const float4* P1 = reinterpret_cast<const float4*>(g_part + NTOK * FEAT);
    float4 a = P0[idx];
    float4 b = P1[idx];
    float4 bb = reinterpret_cast<const float4*>(bias)[idx & 31];
    float4 r;
    r.x = a.x + b.x + bb.x;
    r.y = a.y + b.y + bb.y;
    r.z = a.z + b.z + bb.z;
    r.w = a.w + b.w + bb.w;
    reinterpret_cast<float4*>(out)[idx] = r;
}

// ============================ launch ============================
extern "C" void kernel_launch(void* const* d_in, const int* in_sizes, int n_in,
                              void* d_out, int out_size) {
    const float* x      = (const float*)d_in[0];
    const float* d_list = (const float*)d_in[1];
    const float* U      = (const float*)d_in[2];
    const float* Vt     = (const float*)d_in[3];
    const float* W      = (const float*)d_in[4];
    const float* filt   = (const float*)d_in[5];
    const float* bias   = (const float*)d_in[6];
    float* out = (float*)d_out;

    cudaFuncSetAttribute(xw_kernel, cudaFuncAttributeMaxDynamicSharedMemorySize, 73728);
    cudaFuncSetAttribute(gemm_split_kernel, cudaFuncAttributeMaxDynamicSharedMemorySize, 133120);

    xw_kernel<<<512, 128, 73728>>>(x, W);
    scale_kernel<<<32, 256>>>(d_list, filt);
    gemm_split_kernel<<<dim3(64, 2), 256, 133120>>>(Vt, /*bsel=*/0);
    reduce1_kernel<<<4096, 128>>>();
    gemm_split_kernel<<<dim3(64, 2), 256, 133120>>>(U, /*bsel=*/1);
    reduce2_kernel<<<1024, 256>>>(bias, out);
}